// round 3
// baseline (speedup 1.0000x reference)
#include <cuda_runtime.h>

// Problem constants
#define T_DIM 1024   // time axis (GEMM K)
#define N_QK  256    // q/k head dim
#define N_V   256    // v head dim
#define C_DIM 128    // channels (attention seq len)
#define BD    1024   // B * D independent attention problems
#define M_TOT (BD * C_DIM)  // 131072 projection rows

// Scratch for projected q, k, v (alloc-free rule: __device__ globals)
__device__ float g_q[(size_t)M_TOT * N_QK];
__device__ float g_k[(size_t)M_TOT * N_QK];
__device__ float g_v[(size_t)M_TOT * N_V];

// ---------------------------------------------------------------------------
// Kernel 1: Y[M,256] = X[M,1024] @ W[256,1024]^T + bias
// 128x128 block tile, BK=16, 256 threads, 8x8 microtile, float4 everywhere.
// sel picks destination (0=q, 1=k, 2=v).
// ---------------------------------------------------------------------------
__global__ void __launch_bounds__(256) gemm_qkv(
    const float* __restrict__ X, const float* __restrict__ W,
    const float* __restrict__ bias, int sel)
{
    __shared__ __align__(16) float Xs[16][132];
    __shared__ __align__(16) float Ws[16][132];

    float* __restrict__ Y = (sel == 0) ? g_q : (sel == 1) ? g_k : g_v;

    const int bm  = blockIdx.x;          // 0..1023 (row tile)
    const int bn  = blockIdx.y;          // 0..1    (col tile)
    const int tid = threadIdx.x;
    const int tn  = tid & 15;            // 0..15
    const int tm  = tid >> 4;            // 0..15
    const int lr  = tid >> 2;            // 0..63 (load row)
    const int lc  = (tid & 3) << 2;      // 0,4,8,12 (load col group)

    const float* Xblk = X + (size_t)bm * 128 * T_DIM;
    const float* Wblk = W + (size_t)bn * 128 * T_DIM;

    float acc[8][8];
#pragma unroll
    for (int i = 0; i < 8; i++)
#pragma unroll
        for (int j = 0; j < 8; j++) acc[i][j] = 0.0f;

    for (int k0 = 0; k0 < T_DIM; k0 += 16) {
        float4 xv0 = *(const float4*)(Xblk + (size_t)lr        * T_DIM + k0 + lc);
        float4 xv1 = *(const float4*)(Xblk + (size_t)(lr + 64) * T_DIM + k0 + lc);
        float4 wv0 = *(const float4*)(Wblk + (size_t)lr        * T_DIM + k0 + lc);
        float4 wv1 = *(const float4*)(Wblk + (size_t)(lr + 64) * T_DIM + k0 + lc);

        __syncthreads();   // previous iteration's compute done before overwrite
        Xs[lc + 0][lr]      = xv0.x; Xs[lc + 1][lr]      = xv0.y;
        Xs[lc + 2][lr]      = xv0.z; Xs[lc + 3][lr]      = xv0.w;
        Xs[lc + 0][lr + 64] = xv1.x; Xs[lc + 1][lr + 64] = xv1.y;
        Xs[lc + 2][lr + 64] = xv1.z; Xs[lc + 3][lr + 64] = xv1.w;
        Ws[lc + 0][lr]      = wv0.x; Ws[lc + 1][lr]      = wv0.y;
        Ws[lc + 2][lr]      = wv0.z; Ws[lc + 3][lr]      = wv0.w;
        Ws[lc + 0][lr + 64] = wv1.x; Ws[lc + 1][lr + 64] = wv1.y;
        Ws[lc + 2][lr + 64] = wv1.z; Ws[lc + 3][lr + 64] = wv1.w;
        __syncthreads();

#pragma unroll
        for (int kk = 0; kk < 16; kk++) {
            float4 a0 = *(const float4*)&Xs[kk][tm * 8];
            float4 a1 = *(const float4*)&Xs[kk][tm * 8 + 4];
            float4 b0 = *(const float4*)&Ws[kk][tn * 8];
            float4 b1 = *(const float4*)&Ws[kk][tn * 8 + 4];
            float am[8] = {a0.x, a0.y, a0.z, a0.w, a1.x, a1.y, a1.z, a1.w};
            float bv[8] = {b0.x, b0.y, b0.z, b0.w, b1.x, b1.y, b1.z, b1.w};
#pragma unroll
            for (int i = 0; i < 8; i++)
#pragma unroll
                for (int j = 0; j < 8; j++)
                    acc[i][j] = fmaf(am[i], bv[j], acc[i][j]);
        }
    }

    // Epilogue: add bias, store
    float bb[8];
#pragma unroll
    for (int j = 0; j < 8; j++) bb[j] = bias[bn * 128 + tn * 8 + j];

    float* Yblk = Y + (size_t)bm * 128 * 256 + bn * 128;
#pragma unroll
    for (int i = 0; i < 8; i++) {
        const int row = tm * 8 + i;
        float4 o0 = make_float4(acc[i][0] + bb[0], acc[i][1] + bb[1],
                                acc[i][2] + bb[2], acc[i][3] + bb[3]);
        float4 o1 = make_float4(acc[i][4] + bb[4], acc[i][5] + bb[5],
                                acc[i][6] + bb[6], acc[i][7] + bb[7]);
        *(float4*)(Yblk + (size_t)row * 256 + tn * 8)     = o0;
        *(float4*)(Yblk + (size_t)row * 256 + tn * 8 + 4) = o1;
    }
}

// ---------------------------------------------------------------------------
// Kernel 2: per-(b,d) attention. One CTA per bd.
//   S = q @ k^T / 16   (128x128, acc in regs -> smem)
//   softmax rows of S  (thread-per-row)
//   Z = S @ v          (two 128-col halves)
// Dynamic smem: S[128][129] + two 16x132 tiles = 82944 B
// ---------------------------------------------------------------------------
__global__ void __launch_bounds__(256) attn_kernel(float* __restrict__ out)
{
    extern __shared__ __align__(16) float smem[];
    float* S  = smem;                 // 128*129
    float* As = smem + 128 * 129;     // 16*132
    float* Bs = As + 16 * 132;        // 16*132

    const int bd = blockIdx.x;
    const float* qb = g_q + (size_t)bd * C_DIM * N_QK;
    const float* kb = g_k + (size_t)bd * C_DIM * N_QK;
    const float* vb = g_v + (size_t)bd * C_DIM * N_V;
    float* ob = out + (size_t)bd * C_DIM * N_V;

    const int tid = threadIdx.x;
    const int tn  = tid & 15;
    const int tm  = tid >> 4;
    const int lr  = tid >> 2;
    const int lc  = (tid & 3) << 2;

    // ---- Phase 1: S = q @ k^T ----
    float acc[8][8];
#pragma unroll
    for (int i = 0; i < 8; i++)
#pragma unroll
        for (int j = 0; j < 8; j++) acc[i][j] = 0.0f;

    for (int k0 = 0; k0 < N_QK; k0 += 16) {
        float4 q0 = *(const float4*)(qb + (size_t)lr        * N_QK + k0 + lc);
        float4 q1 = *(const float4*)(qb + (size_t)(lr + 64) * N_QK + k0 + lc);
        float4 kk0 = *(const float4*)(kb + (size_t)lr        * N_QK + k0 + lc);
        float4 kk1 = *(const float4*)(kb + (size_t)(lr + 64) * N_QK + k0 + lc);

        __syncthreads();
        As[(lc + 0) * 132 + lr]      = q0.x; As[(lc + 1) * 132 + lr]      = q0.y;
        As[(lc + 2) * 132 + lr]      = q0.z; As[(lc + 3) * 132 + lr]      = q0.w;
        As[(lc + 0) * 132 + lr + 64] = q1.x; As[(lc + 1) * 132 + lr + 64] = q1.y;
        As[(lc + 2) * 132 + lr + 64] = q1.z; As[(lc + 3) * 132 + lr + 64] = q1.w;
        Bs[(lc + 0) * 132 + lr]      = kk0.x; Bs[(lc + 1) * 132 + lr]      = kk0.y;
        Bs[(lc + 2) * 132 + lr]      = kk0.z; Bs[(lc + 3) * 132 + lr]      = kk0.w;
        Bs[(lc + 0) * 132 + lr + 64] = kk1.x; Bs[(lc + 1) * 132 + lr + 64] = kk1.y;
        Bs[(lc + 2) * 132 + lr + 64] = kk1.z; Bs[(lc + 3) * 132 + lr + 64] = kk1.w;
        __syncthreads();

#pragma unroll
        for (int kk = 0; kk < 16; kk++) {
            float4 a0 = *(const float4*)&As[kk * 132 + tm * 8];
            float4 a1 = *(const float4*)&As[kk * 132 + tm * 8 + 4];
            float4 b0 = *(const float4*)&Bs[kk * 132 + tn * 8];
            float4 b1 = *(const float4*)&Bs[kk * 132 + tn * 8 + 4];
            float am[8] = {a0.x, a0.y, a0.z, a0.w, a1.x, a1.y, a1.z, a1.w};
            float bv[8] = {b0.x, b0.y, b0.z, b0.w, b1.x, b1.y, b1.z, b1.w};
#pragma unroll
            for (int i = 0; i < 8; i++)
#pragma unroll
                for (int j = 0; j < 8; j++)
                    acc[i][j] = fmaf(am[i], bv[j], acc[i][j]);
        }
    }

    const float scale = 0.0625f;  // 1/sqrt(256)
#pragma unroll
    for (int i = 0; i < 8; i++)
#pragma unroll
        for (int j = 0; j < 8; j++)
            S[(size_t)(tm * 8 + i) * 129 + tn * 8 + j] = acc[i][j] * scale;
    __syncthreads();

    // ---- Phase 2: row softmax (thread t owns row t) ----
    if (tid < 128) {
        float* row = &S[(size_t)tid * 129];
        float m = -1e30f;
        for (int j = 0; j < 128; j++) m = fmaxf(m, row[j]);
        float s = 0.0f;
        for (int j = 0; j < 128; j++) { float e = __expf(row[j] - m); row[j] = e; s += e; }
        float inv = 1.0f / s;
        for (int j = 0; j < 128; j++) row[j] *= inv;
    }
    __syncthreads();

    // ---- Phase 3: Z = S @ v, two 128-col halves ----
#pragma unroll
    for (int h = 0; h < 2; h++) {
        float z[8][8];
#pragma unroll
        for (int i = 0; i < 8; i++)
#pragma unroll
            for (int j = 0; j < 8; j++) z[i][j] = 0.0f;

        for (int j0 = 0; j0 < 128; j0 += 16) {
            const int vr = tid >> 5;          // 0..7
            const int vc = (tid & 31) << 2;   // 0..124
            float4 v0 = *(const float4*)(vb + (size_t)(j0 + vr)     * N_V + h * 128 + vc);
            float4 v1 = *(const float4*)(vb + (size_t)(j0 + vr + 8) * N_V + h * 128 + vc);
            __syncthreads();
            *(float4*)&Bs[(vr)     * 132 + vc] = v0;
            *(float4*)&Bs[(vr + 8) * 132 + vc] = v1;
            __syncthreads();

#pragma unroll
            for (int jj = 0; jj < 16; jj++) {
                float a[8];
#pragma unroll
                for (int i = 0; i < 8; i++)
                    a[i] = S[(size_t)(tm * 8 + i) * 129 + j0 + jj];
                float4 b0 = *(const float4*)&Bs[jj * 132 + tn * 8];
                float4 b1 = *(const float4*)&Bs[jj * 132 + tn * 8 + 4];
                float bv[8] = {b0.x, b0.y, b0.z, b0.w, b1.x, b1.y, b1.z, b1.w};
#pragma unroll
                for (int i = 0; i < 8; i++)
#pragma unroll
                    for (int j = 0; j < 8; j++)
                        z[i][j] = fmaf(a[i], bv[j], z[i][j]);
            }
        }

#pragma unroll
        for (int i = 0; i < 8; i++) {
            float4 o0 = make_float4(z[i][0], z[i][1], z[i][2], z[i][3]);
            float4 o1 = make_float4(z[i][4], z[i][5], z[i][6], z[i][7]);
            *(float4*)(ob + (size_t)(tm * 8 + i) * N_V + h * 128 + tn * 8)     = o0;
            *(float4*)(ob + (size_t)(tm * 8 + i) * N_V + h * 128 + tn * 8 + 4) = o1;
        }
    }
}

// ---------------------------------------------------------------------------
extern "C" void kernel_launch(void* const* d_in, const int* in_sizes, int n_in,
                              void* d_out, int out_size)
{
    const float* x  = (const float*)d_in[0];
    const float* Wq = (const float*)d_in[1];
    const float* bq = (const float*)d_in[2];
    const float* Wk = (const float*)d_in[3];
    const float* bk = (const float*)d_in[4];
    const float* Wv = (const float*)d_in[5];
    const float* bv = (const float*)d_in[6];
    float* out = (float*)d_out;

    dim3 grid1(M_TOT / 128, 2);
    gemm_qkv<<<grid1, 256>>>(x, Wq, bq, 0);
    gemm_qkv<<<grid1, 256>>>(x, Wk, bk, 1);
    gemm_qkv<<<grid1, 256>>>(x, Wv, bv, 2);

    const size_t smem2 = (size_t)(128 * 129 + 2 * 16 * 132) * sizeof(float);
    cudaFuncSetAttribute(attn_kernel, cudaFuncAttributeMaxDynamicSharedMemorySize,
                         (int)smem2);
    attn_kernel<<<BD, 256, smem2>>>(out);
}

// round 4
// speedup vs baseline: 1.0015x; 1.0015x over previous
#include <cuda_runtime.h>

// Problem constants
#define T_DIM 1024   // time axis (GEMM K)
#define N_QK  256    // q/k head dim
#define N_V   256    // v head dim
#define C_DIM 128    // channels (attention seq len)
#define BD    1024   // B * D independent attention problems
#define M_TOT (BD * C_DIM)  // 131072 projection rows

// Scratch for projected q, k, v (alloc-free rule: __device__ globals)
__device__ float g_q[(size_t)M_TOT * N_QK];
__device__ float g_k[(size_t)M_TOT * N_QK];
__device__ float g_v[(size_t)M_TOT * N_V];

// ---------------------------------------------------------------------------
// Kernel 1: Y[M,256] = X[M,1024] @ W[256,1024]^T + bias
// 128x128 block tile, BK=16, 256 threads, 8x8 microtile, float4 everywhere.
// sel picks destination (0=q, 1=k, 2=v).
// ---------------------------------------------------------------------------
__global__ void __launch_bounds__(256) gemm_qkv(
    const float* __restrict__ X, const float* __restrict__ W,
    const float* __restrict__ bias, int sel)
{
    __shared__ __align__(16) float Xs[16][132];
    __shared__ __align__(16) float Ws[16][132];

    float* __restrict__ Y = (sel == 0) ? g_q : (sel == 1) ? g_k : g_v;

    const int bm  = blockIdx.x;          // 0..1023 (row tile)
    const int bn  = blockIdx.y;          // 0..1    (col tile)
    const int tid = threadIdx.x;
    const int tn  = tid & 15;            // 0..15
    const int tm  = tid >> 4;            // 0..15
    const int lr  = tid >> 2;            // 0..63 (load row)
    const int lc  = (tid & 3) << 2;      // 0,4,8,12 (load col group)

    const float* Xblk = X + (size_t)bm * 128 * T_DIM;
    const float* Wblk = W + (size_t)bn * 128 * T_DIM;

    float acc[8][8];
#pragma unroll
    for (int i = 0; i < 8; i++)
#pragma unroll
        for (int j = 0; j < 8; j++) acc[i][j] = 0.0f;

    for (int k0 = 0; k0 < T_DIM; k0 += 16) {
        float4 xv0 = *(const float4*)(Xblk + (size_t)lr        * T_DIM + k0 + lc);
        float4 xv1 = *(const float4*)(Xblk + (size_t)(lr + 64) * T_DIM + k0 + lc);
        float4 wv0 = *(const float4*)(Wblk + (size_t)lr        * T_DIM + k0 + lc);
        float4 wv1 = *(const float4*)(Wblk + (size_t)(lr + 64) * T_DIM + k0 + lc);

        __syncthreads();   // previous iteration's compute done before overwrite
        Xs[lc + 0][lr]      = xv0.x; Xs[lc + 1][lr]      = xv0.y;
        Xs[lc + 2][lr]      = xv0.z; Xs[lc + 3][lr]      = xv0.w;
        Xs[lc + 0][lr + 64] = xv1.x; Xs[lc + 1][lr + 64] = xv1.y;
        Xs[lc + 2][lr + 64] = xv1.z; Xs[lc + 3][lr + 64] = xv1.w;
        Ws[lc + 0][lr]      = wv0.x; Ws[lc + 1][lr]      = wv0.y;
        Ws[lc + 2][lr]      = wv0.z; Ws[lc + 3][lr]      = wv0.w;
        Ws[lc + 0][lr + 64] = wv1.x; Ws[lc + 1][lr + 64] = wv1.y;
        Ws[lc + 2][lr + 64] = wv1.z; Ws[lc + 3][lr + 64] = wv1.w;
        __syncthreads();

#pragma unroll
        for (int kk = 0; kk < 16; kk++) {
            float4 a0 = *(const float4*)&Xs[kk][tm * 8];
            float4 a1 = *(const float4*)&Xs[kk][tm * 8 + 4];
            float4 b0 = *(const float4*)&Ws[kk][tn * 8];
            float4 b1 = *(const float4*)&Ws[kk][tn * 8 + 4];
            float am[8] = {a0.x, a0.y, a0.z, a0.w, a1.x, a1.y, a1.z, a1.w};
            float bv[8] = {b0.x, b0.y, b0.z, b0.w, b1.x, b1.y, b1.z, b1.w};
#pragma unroll
            for (int i = 0; i < 8; i++)
#pragma unroll
                for (int j = 0; j < 8; j++)
                    acc[i][j] = fmaf(am[i], bv[j], acc[i][j]);
        }
    }

    // Epilogue: add bias, store
    float bb[8];
#pragma unroll
    for (int j = 0; j < 8; j++) bb[j] = bias[bn * 128 + tn * 8 + j];

    float* Yblk = Y + (size_t)bm * 128 * 256 + bn * 128;
#pragma unroll
    for (int i = 0; i < 8; i++) {
        const int row = tm * 8 + i;
        float4 o0 = make_float4(acc[i][0] + bb[0], acc[i][1] + bb[1],
                                acc[i][2] + bb[2], acc[i][3] + bb[3]);
        float4 o1 = make_float4(acc[i][4] + bb[4], acc[i][5] + bb[5],
                                acc[i][6] + bb[6], acc[i][7] + bb[7]);
        *(float4*)(Yblk + (size_t)row * 256 + tn * 8)     = o0;
        *(float4*)(Yblk + (size_t)row * 256 + tn * 8 + 4) = o1;
    }
}

// ---------------------------------------------------------------------------
// Kernel 2: per-(b,d) attention. One CTA per bd.
//   S = q @ k^T / 16   (128x128, acc in regs -> smem)
//   softmax rows of S  (thread-per-row)
//   Z = S @ v          (two 128-col halves)
// Dynamic smem: S[128][129] + two 16x132 tiles = 82944 B
// ---------------------------------------------------------------------------
__global__ void __launch_bounds__(256) attn_kernel(float* __restrict__ out)
{
    extern __shared__ __align__(16) float smem[];
    float* S  = smem;                 // 128*129
    float* As = smem + 128 * 129;     // 16*132
    float* Bs = As + 16 * 132;        // 16*132

    const int bd = blockIdx.x;
    const float* qb = g_q + (size_t)bd * C_DIM * N_QK;
    const float* kb = g_k + (size_t)bd * C_DIM * N_QK;
    const float* vb = g_v + (size_t)bd * C_DIM * N_V;
    float* ob = out + (size_t)bd * C_DIM * N_V;

    const int tid = threadIdx.x;
    const int tn  = tid & 15;
    const int tm  = tid >> 4;
    const int lr  = tid >> 2;
    const int lc  = (tid & 3) << 2;

    // ---- Phase 1: S = q @ k^T ----
    float acc[8][8];
#pragma unroll
    for (int i = 0; i < 8; i++)
#pragma unroll
        for (int j = 0; j < 8; j++) acc[i][j] = 0.0f;

    for (int k0 = 0; k0 < N_QK; k0 += 16) {
        float4 q0 = *(const float4*)(qb + (size_t)lr        * N_QK + k0 + lc);
        float4 q1 = *(const float4*)(qb + (size_t)(lr + 64) * N_QK + k0 + lc);
        float4 kk0 = *(const float4*)(kb + (size_t)lr        * N_QK + k0 + lc);
        float4 kk1 = *(const float4*)(kb + (size_t)(lr + 64) * N_QK + k0 + lc);

        __syncthreads();
        As[(lc + 0) * 132 + lr]      = q0.x; As[(lc + 1) * 132 + lr]      = q0.y;
        As[(lc + 2) * 132 + lr]      = q0.z; As[(lc + 3) * 132 + lr]      = q0.w;
        As[(lc + 0) * 132 + lr + 64] = q1.x; As[(lc + 1) * 132 + lr + 64] = q1.y;
        As[(lc + 2) * 132 + lr + 64] = q1.z; As[(lc + 3) * 132 + lr + 64] = q1.w;
        Bs[(lc + 0) * 132 + lr]      = kk0.x; Bs[(lc + 1) * 132 + lr]      = kk0.y;
        Bs[(lc + 2) * 132 + lr]      = kk0.z; Bs[(lc + 3) * 132 + lr]      = kk0.w;
        Bs[(lc + 0) * 132 + lr + 64] = kk1.x; Bs[(lc + 1) * 132 + lr + 64] = kk1.y;
        Bs[(lc + 2) * 132 + lr + 64] = kk1.z; Bs[(lc + 3) * 132 + lr + 64] = kk1.w;
        __syncthreads();

#pragma unroll
        for (int kk = 0; kk < 16; kk++) {
            float4 a0 = *(const float4*)&As[kk * 132 + tm * 8];
            float4 a1 = *(const float4*)&As[kk * 132 + tm * 8 + 4];
            float4 b0 = *(const float4*)&Bs[kk * 132 + tn * 8];
            float4 b1 = *(const float4*)&Bs[kk * 132 + tn * 8 + 4];
            float am[8] = {a0.x, a0.y, a0.z, a0.w, a1.x, a1.y, a1.z, a1.w};
            float bv[8] = {b0.x, b0.y, b0.z, b0.w, b1.x, b1.y, b1.z, b1.w};
#pragma unroll
            for (int i = 0; i < 8; i++)
#pragma unroll
                for (int j = 0; j < 8; j++)
                    acc[i][j] = fmaf(am[i], bv[j], acc[i][j]);
        }
    }

    const float scale = 0.0625f;  // 1/sqrt(256)
#pragma unroll
    for (int i = 0; i < 8; i++)
#pragma unroll
        for (int j = 0; j < 8; j++)
            S[(size_t)(tm * 8 + i) * 129 + tn * 8 + j] = acc[i][j] * scale;
    __syncthreads();

    // ---- Phase 2: row softmax (thread t owns row t) ----
    if (tid < 128) {
        float* row = &S[(size_t)tid * 129];
        float m = -1e30f;
        for (int j = 0; j < 128; j++) m = fmaxf(m, row[j]);
        float s = 0.0f;
        for (int j = 0; j < 128; j++) { float e = __expf(row[j] - m); row[j] = e; s += e; }
        float inv = 1.0f / s;
        for (int j = 0; j < 128; j++) row[j] *= inv;
    }
    __syncthreads();

    // ---- Phase 3: Z = S @ v, two 128-col halves ----
#pragma unroll
    for (int h = 0; h < 2; h++) {
        float z[8][8];
#pragma unroll
        for (int i = 0; i < 8; i++)
#pragma unroll
            for (int j = 0; j < 8; j++) z[i][j] = 0.0f;

        for (int j0 = 0; j0 < 128; j0 += 16) {
            const int vr = tid >> 5;          // 0..7
            const int vc = (tid & 31) << 2;   // 0..124
            float4 v0 = *(const float4*)(vb + (size_t)(j0 + vr)     * N_V + h * 128 + vc);
            float4 v1 = *(const float4*)(vb + (size_t)(j0 + vr + 8) * N_V + h * 128 + vc);
            __syncthreads();
            *(float4*)&Bs[(vr)     * 132 + vc] = v0;
            *(float4*)&Bs[(vr + 8) * 132 + vc] = v1;
            __syncthreads();

#pragma unroll
            for (int jj = 0; jj < 16; jj++) {
                float a[8];
#pragma unroll
                for (int i = 0; i < 8; i++)
                    a[i] = S[(size_t)(tm * 8 + i) * 129 + j0 + jj];
                float4 b0 = *(const float4*)&Bs[jj * 132 + tn * 8];
                float4 b1 = *(const float4*)&Bs[jj * 132 + tn * 8 + 4];
                float bv[8] = {b0.x, b0.y, b0.z, b0.w, b1.x, b1.y, b1.z, b1.w};
#pragma unroll
                for (int i = 0; i < 8; i++)
#pragma unroll
                    for (int j = 0; j < 8; j++)
                        z[i][j] = fmaf(a[i], bv[j], z[i][j]);
            }
        }

#pragma unroll
        for (int i = 0; i < 8; i++) {
            float4 o0 = make_float4(z[i][0], z[i][1], z[i][2], z[i][3]);
            float4 o1 = make_float4(z[i][4], z[i][5], z[i][6], z[i][7]);
            *(float4*)(ob + (size_t)(tm * 8 + i) * N_V + h * 128 + tn * 8)     = o0;
            *(float4*)(ob + (size_t)(tm * 8 + i) * N_V + h * 128 + tn * 8 + 4) = o1;
        }
    }
}

// ---------------------------------------------------------------------------
extern "C" void kernel_launch(void* const* d_in, const int* in_sizes, int n_in,
                              void* d_out, int out_size)
{
    const float* x  = (const float*)d_in[0];
    const float* Wq = (const float*)d_in[1];
    const float* bq = (const float*)d_in[2];
    const float* Wk = (const float*)d_in[3];
    const float* bk = (const float*)d_in[4];
    const float* Wv = (const float*)d_in[5];
    const float* bv = (const float*)d_in[6];
    float* out = (float*)d_out;

    dim3 grid1(M_TOT / 128, 2);
    gemm_qkv<<<grid1, 256>>>(x, Wq, bq, 0);
    gemm_qkv<<<grid1, 256>>>(x, Wk, bk, 1);
    gemm_qkv<<<grid1, 256>>>(x, Wv, bv, 2);

    const size_t smem2 = (size_t)(128 * 129 + 2 * 16 * 132) * sizeof(float);
    cudaFuncSetAttribute(attn_kernel, cudaFuncAttributeMaxDynamicSharedMemorySize,
                         (int)smem2);
    attn_kernel<<<BD, 256, smem2>>>(out);
}

// round 6
// speedup vs baseline: 2.3047x; 2.3013x over previous
#include <cuda_runtime.h>
#include <cuda_bf16.h>
#include <cstdint>

// Problem constants
#define T_DIM 1024
#define N_QK  256
#define N_V   256
#define C_DIM 128
#define BD    1024
#define M_TOT (BD * C_DIM)   // 131072

// ---------------------------------------------------------------------------
// Scratch (__device__ globals; alloc-free rule)
// ---------------------------------------------------------------------------
__device__ float g_q[(size_t)M_TOT * N_QK];
__device__ float g_k[(size_t)M_TOT * N_QK];
__device__ float g_v[(size_t)M_TOT * N_V];

__device__ __align__(16) __nv_bfloat16 g_xh[(size_t)M_TOT * T_DIM];
__device__ __align__(16) __nv_bfloat16 g_xl[(size_t)M_TOT * T_DIM];
__device__ __align__(16) __nv_bfloat16 g_wh[3 * 256 * T_DIM];
__device__ __align__(16) __nv_bfloat16 g_wl[3 * 256 * T_DIM];

// ---------------------------------------------------------------------------
// Helpers
// ---------------------------------------------------------------------------
__device__ __forceinline__ uint32_t smem_u32(const void* p) {
    uint32_t a;
    asm("{ .reg .u64 t; cvta.to.shared.u64 t, %1; cvt.u32.u64 %0, t; }"
        : "=r"(a) : "l"(p));
    return a;
}
__device__ __forceinline__ void cp16(uint32_t dst, const void* src) {
    asm volatile("cp.async.cg.shared.global [%0], [%1], 16;"
                 :: "r"(dst), "l"(src) : "memory");
}
#define CP_COMMIT() asm volatile("cp.async.commit_group;" ::: "memory")
#define CP_WAIT1()  asm volatile("cp.async.wait_group 1;" ::: "memory")

__device__ __forceinline__ void ldsm4(uint32_t* r, uint32_t addr) {
    asm volatile("ldmatrix.sync.aligned.m8n8.x4.shared.b16 {%0,%1,%2,%3}, [%4];"
                 : "=r"(r[0]), "=r"(r[1]), "=r"(r[2]), "=r"(r[3]) : "r"(addr));
}
__device__ __forceinline__ void mma16816(float* d, const uint32_t* a,
                                         uint32_t b0, uint32_t b1) {
    asm volatile(
        "mma.sync.aligned.m16n8k16.row.col.f32.bf16.bf16.f32 "
        "{%0,%1,%2,%3}, {%4,%5,%6,%7}, {%8,%9}, {%0,%1,%2,%3};"
        : "+f"(d[0]), "+f"(d[1]), "+f"(d[2]), "+f"(d[3])
        : "r"(a[0]), "r"(a[1]), "r"(a[2]), "r"(a[3]), "r"(b0), "r"(b1));
}

// ---------------------------------------------------------------------------
// Convert kernels: fp32 -> bf16 hi/lo split
// ---------------------------------------------------------------------------
__device__ __forceinline__ uint32_t pack_bf2(__nv_bfloat16 a, __nv_bfloat16 b) {
    return (uint32_t)__bfloat16_as_ushort(a) | ((uint32_t)__bfloat16_as_ushort(b) << 16);
}

__global__ void __launch_bounds__(256) conv_x(const float* __restrict__ x)
{
    const size_t n4 = (size_t)M_TOT * T_DIM / 4;
    const size_t stride = (size_t)gridDim.x * blockDim.x;
    uint2* __restrict__ xh = (uint2*)g_xh;
    uint2* __restrict__ xl = (uint2*)g_xl;
    for (size_t i = (size_t)blockIdx.x * blockDim.x + threadIdx.x; i < n4; i += stride) {
        float4 f = ((const float4*)x)[i];
        __nv_bfloat16 h0 = __float2bfloat16(f.x);
        __nv_bfloat16 h1 = __float2bfloat16(f.y);
        __nv_bfloat16 h2 = __float2bfloat16(f.z);
        __nv_bfloat16 h3 = __float2bfloat16(f.w);
        __nv_bfloat16 l0 = __float2bfloat16(f.x - __bfloat162float(h0));
        __nv_bfloat16 l1 = __float2bfloat16(f.y - __bfloat162float(h1));
        __nv_bfloat16 l2 = __float2bfloat16(f.z - __bfloat162float(h2));
        __nv_bfloat16 l3 = __float2bfloat16(f.w - __bfloat162float(h3));
        xh[i] = make_uint2(pack_bf2(h0, h1), pack_bf2(h2, h3));
        xl[i] = make_uint2(pack_bf2(l0, l1), pack_bf2(l2, l3));
    }
}

__global__ void __launch_bounds__(256) conv_w(const float* __restrict__ Wq,
                                              const float* __restrict__ Wk,
                                              const float* __restrict__ Wv)
{
    const int mat = blockIdx.y;
    const float* W = (mat == 0) ? Wq : (mat == 1) ? Wk : Wv;
    const size_t n4 = 256 * T_DIM / 4;
    const size_t base = (size_t)mat * n4;
    uint2* __restrict__ wh = (uint2*)g_wh;
    uint2* __restrict__ wl = (uint2*)g_wl;
    for (size_t i = (size_t)blockIdx.x * blockDim.x + threadIdx.x; i < n4;
         i += (size_t)gridDim.x * blockDim.x) {
        float4 f = ((const float4*)W)[i];
        __nv_bfloat16 h0 = __float2bfloat16(f.x);
        __nv_bfloat16 h1 = __float2bfloat16(f.y);
        __nv_bfloat16 h2 = __float2bfloat16(f.z);
        __nv_bfloat16 h3 = __float2bfloat16(f.w);
        __nv_bfloat16 l0 = __float2bfloat16(f.x - __bfloat162float(h0));
        __nv_bfloat16 l1 = __float2bfloat16(f.y - __bfloat162float(h1));
        __nv_bfloat16 l2 = __float2bfloat16(f.z - __bfloat162float(h2));
        __nv_bfloat16 l3 = __float2bfloat16(f.w - __bfloat162float(h3));
        wh[base + i] = make_uint2(pack_bf2(h0, h1), pack_bf2(h2, h3));
        wl[base + i] = make_uint2(pack_bf2(l0, l1), pack_bf2(l2, l3));
    }
}

// ---------------------------------------------------------------------------
// HMMA GEMM: Y[128,128] tile = X[128,1024] @ W[128rows,1024]^T + bias
//   bf16 split: Y = Xh@Wh + Xh@Wl + Xl@Wh  (fp32 accumulate in registers)
// grid = (6 = mat*2 + ntile, 1024 = mtile), 256 threads (8 warps, 2x4 grid)
// smem per stage: 4 tiles (Ah/Al/Bh/Bl), each 128 rows x 32 bf16, row
// stride 80B (conflict-free for ldmatrix). 2 stages, cp.async pipeline.
// ---------------------------------------------------------------------------
#define ROW_B   80          // bytes per smem tile row (32 bf16 = 64B + pad)
#define TILE_B  (128 * ROW_B)       // 10240
#define OFF_AH  0
#define OFF_AL  (1 * TILE_B)
#define OFF_BH  (2 * TILE_B)
#define OFF_BL  (3 * TILE_B)
#define STAGE_B (4 * TILE_B)        // 40960
#define GEMM_SMEM (2 * STAGE_B)     // 81920
#define NCHUNK  32                  // K=1024 / BK=32

__device__ __forceinline__ void load_chunk(
    uint32_t st, const __nv_bfloat16* __restrict__ xh,
    const __nv_bfloat16* __restrict__ xl,
    const __nv_bfloat16* __restrict__ wh,
    const __nv_bfloat16* __restrict__ wl, int k0, int tid)
{
#pragma unroll
    for (int t = 0; t < 2; t++) {
        int op = tid + t * 256;
        int r  = op >> 2;          // 0..127
        int ch = op & 3;           // 0..3 (16B chunks)
        uint32_t doff = (uint32_t)(r * ROW_B + ch * 16);
        size_t soff = (size_t)r * T_DIM + k0 + ch * 8;
        cp16(st + OFF_AH + doff, xh + soff);
        cp16(st + OFF_AL + doff, xl + soff);
        cp16(st + OFF_BH + doff, wh + soff);
        cp16(st + OFF_BL + doff, wl + soff);
    }
}

__global__ void __launch_bounds__(256, 2) gemm_mma(
    const float* __restrict__ bq, const float* __restrict__ bk,
    const float* __restrict__ bv)
{
    extern __shared__ __align__(16) char dyn[];

    const int tid  = threadIdx.x;
    const int wid  = tid >> 5;
    const int lane = tid & 31;
    const int mat  = blockIdx.x >> 1;   // 0..2
    const int bn   = blockIdx.x & 1;    // 0..1 (n tile of 128)
    const int bm   = blockIdx.y;        // 0..1023

    const int wm = (wid >> 2) * 64;     // 0 or 64
    const int wn = (wid & 3) * 32;      // 0,32,64,96

    const __nv_bfloat16* xh = g_xh + (size_t)bm * 128 * T_DIM;
    const __nv_bfloat16* xl = g_xl + (size_t)bm * 128 * T_DIM;
    const __nv_bfloat16* wh = g_wh + ((size_t)mat * 256 + bn * 128) * T_DIM;
    const __nv_bfloat16* wl = g_wl + ((size_t)mat * 256 + bn * 128) * T_DIM;
    const float* bias = (mat == 0) ? bq : (mat == 1) ? bk : bv;
    float* outp = ((mat == 0) ? g_q : (mat == 1) ? g_k : g_v)
                  + (size_t)bm * 128 * 256 + bn * 128;

    const uint32_t sbase = smem_u32(dyn);

    float acc[4][4][4];
#pragma unroll
    for (int i = 0; i < 4; i++)
#pragma unroll
        for (int j = 0; j < 4; j++)
#pragma unroll
            for (int r = 0; r < 4; r++) acc[i][j][r] = 0.0f;

    // Per-lane ldmatrix base offsets (within a tile)
    // A x4: lanes 0-7 rows m0-7 k0-7 | 8-15 rows m8-15 k0-7 |
    //       16-23 rows m0-7 k8-15 | 24-31 rows m8-15 k8-15
    const uint32_t aoff = (uint32_t)((wm + (lane & 15)) * ROW_B + (lane >> 4) * 16);
    // B x4: lanes 0-7 n0-7 k0-7 | 8-15 n0-7 k8-15 | 16-23 n8-15 k0-7 | 24-31 n8-15 k8-15
    const uint32_t boff = (uint32_t)((wn + ((lane >> 4) << 3) + (lane & 7)) * ROW_B
                                     + ((lane >> 3) & 1) * 16);

    // Prologue
    load_chunk(sbase + 0 * STAGE_B, xh, xl, wh, wl, 0, tid);
    CP_COMMIT();
    load_chunk(sbase + 1 * STAGE_B, xh, xl, wh, wl, 32, tid);
    CP_COMMIT();

    for (int c = 0; c < NCHUNK; c++) {
        const uint32_t st = sbase + (c & 1) * STAGE_B;
        CP_WAIT1();
        __syncthreads();

#pragma unroll
        for (int ks = 0; ks < 2; ks++) {
            const uint32_t kadd = (uint32_t)(ks * 32);   // 16 bf16 = 32B
            uint32_t ah[4][4], bh[2][4];
#pragma unroll
            for (int mi = 0; mi < 4; mi++)
                ldsm4(ah[mi], st + OFF_AH + aoff + mi * (16 * ROW_B) + kadd);
#pragma unroll
            for (int np = 0; np < 2; np++)
                ldsm4(bh[np], st + OFF_BH + boff + np * (16 * ROW_B) + kadd);
#pragma unroll
            for (int mi = 0; mi < 4; mi++)
#pragma unroll
                for (int nj = 0; nj < 4; nj++)
                    mma16816(acc[mi][nj], ah[mi], bh[nj >> 1][(nj & 1) * 2],
                             bh[nj >> 1][(nj & 1) * 2 + 1]);

            uint32_t bl[2][4];
#pragma unroll
            for (int np = 0; np < 2; np++)
                ldsm4(bl[np], st + OFF_BL + boff + np * (16 * ROW_B) + kadd);
#pragma unroll
            for (int mi = 0; mi < 4; mi++)
#pragma unroll
                for (int nj = 0; nj < 4; nj++)
                    mma16816(acc[mi][nj], ah[mi], bl[nj >> 1][(nj & 1) * 2],
                             bl[nj >> 1][(nj & 1) * 2 + 1]);

            uint32_t al[4][4];
#pragma unroll
            for (int mi = 0; mi < 4; mi++)
                ldsm4(al[mi], st + OFF_AL + aoff + mi * (16 * ROW_B) + kadd);
#pragma unroll
            for (int mi = 0; mi < 4; mi++)
#pragma unroll
                for (int nj = 0; nj < 4; nj++)
                    mma16816(acc[mi][nj], al[mi], bh[nj >> 1][(nj & 1) * 2],
                             bh[nj >> 1][(nj & 1) * 2 + 1]);
        }

        __syncthreads();
        if (c + 2 < NCHUNK)
            load_chunk(st, xh, xl, wh, wl, (c + 2) * 32, tid);
        CP_COMMIT();   // uniform group count (possibly empty)
    }

    // Epilogue: acc -> gmem with bias
    const int rq = lane >> 2;          // row within 16-tile (0..7)
    const int cq = (lane & 3) * 2;     // col within 8-tile
#pragma unroll
    for (int nj = 0; nj < 4; nj++) {
        const int col = wn + nj * 8 + cq;
        const float b0 = bias[bn * 128 + col];
        const float b1 = bias[bn * 128 + col + 1];
#pragma unroll
        for (int mi = 0; mi < 4; mi++) {
            const int row = wm + mi * 16 + rq;
            float2 o0 = make_float2(acc[mi][nj][0] + b0, acc[mi][nj][1] + b1);
            float2 o1 = make_float2(acc[mi][nj][2] + b0, acc[mi][nj][3] + b1);
            *(float2*)(outp + (size_t)row * 256 + col)       = o0;
            *(float2*)(outp + (size_t)(row + 8) * 256 + col) = o1;
        }
    }
}

// ---------------------------------------------------------------------------
// Attention kernel (unchanged): one CTA per (b,d)
// ---------------------------------------------------------------------------
__global__ void __launch_bounds__(256) attn_kernel(float* __restrict__ out)
{
    extern __shared__ __align__(16) float smem[];
    float* S  = smem;                 // 128*129
    float* As = smem + 128 * 129;     // 16*132
    float* Bs = As + 16 * 132;        // 16*132

    const int bd = blockIdx.x;
    const float* qb = g_q + (size_t)bd * C_DIM * N_QK;
    const float* kb = g_k + (size_t)bd * C_DIM * N_QK;
    const float* vb = g_v + (size_t)bd * C_DIM * N_V;
    float* ob = out + (size_t)bd * C_DIM * N_V;

    const int tid = threadIdx.x;
    const int tn  = tid & 15;
    const int tm  = tid >> 4;
    const int lr  = tid >> 2;
    const int lc  = (tid & 3) << 2;

    float acc[8][8];
#pragma unroll
    for (int i = 0; i < 8; i++)
#pragma unroll
        for (int j = 0; j < 8; j++) acc[i][j] = 0.0f;

    for (int k0 = 0; k0 < N_QK; k0 += 16) {
        float4 q0 = *(const float4*)(qb + (size_t)lr        * N_QK + k0 + lc);
        float4 q1 = *(const float4*)(qb + (size_t)(lr + 64) * N_QK + k0 + lc);
        float4 kk0 = *(const float4*)(kb + (size_t)lr        * N_QK + k0 + lc);
        float4 kk1 = *(const float4*)(kb + (size_t)(lr + 64) * N_QK + k0 + lc);

        __syncthreads();
        As[(lc + 0) * 132 + lr]      = q0.x; As[(lc + 1) * 132 + lr]      = q0.y;
        As[(lc + 2) * 132 + lr]      = q0.z; As[(lc + 3) * 132 + lr]      = q0.w;
        As[(lc + 0) * 132 + lr + 64] = q1.x; As[(lc + 1) * 132 + lr + 64] = q1.y;
        As[(lc + 2) * 132 + lr + 64] = q1.z; As[(lc + 3) * 132 + lr + 64] = q1.w;
        Bs[(lc + 0) * 132 + lr]      = kk0.x; Bs[(lc + 1) * 132 + lr]      = kk0.y;
        Bs[(lc + 2) * 132 + lr]      = kk0.z; Bs[(lc + 3) * 132 + lr]      = kk0.w;
        Bs[(lc + 0) * 132 + lr + 64] = kk1.x; Bs[(lc + 1) * 132 + lr + 64] = kk1.y;
        Bs[(lc + 2) * 132 + lr + 64] = kk1.z; Bs[(lc + 3) * 132 + lr + 64] = kk1.w;
        __syncthreads();

#pragma unroll
        for (int kk = 0; kk < 16; kk++) {
            float4 a0 = *(const float4*)&As[kk * 132 + tm * 8];
            float4 a1 = *(const float4*)&As[kk * 132 + tm * 8 + 4];
            float4 b0 = *(const float4*)&Bs[kk * 132 + tn * 8];
            float4 b1 = *(const float4*)&Bs[kk * 132 + tn * 8 + 4];
            float am[8] = {a0.x, a0.y, a0.z, a0.w, a1.x, a1.y, a1.z, a1.w};
            float bvv[8] = {b0.x, b0.y, b0.z, b0.w, b1.x, b1.y, b1.z, b1.w};
#pragma unroll
            for (int i = 0; i < 8; i++)
#pragma unroll
                for (int j = 0; j < 8; j++)
                    acc[i][j] = fmaf(am[i], bvv[j], acc[i][j]);
        }
    }

    const float scale = 0.0625f;
#pragma unroll
    for (int i = 0; i < 8; i++)
#pragma unroll
        for (int j = 0; j < 8; j++)
            S[(size_t)(tm * 8 + i) * 129 + tn * 8 + j] = acc[i][j] * scale;
    __syncthreads();

    if (tid < 128) {
        float* row = &S[(size_t)tid * 129];
        float m = -1e30f;
        for (int j = 0; j < 128; j++) m = fmaxf(m, row[j]);
        float s = 0.0f;
        for (int j = 0; j < 128; j++) { float e = __expf(row[j] - m); row[j] = e; s += e; }
        float inv = 1.0f / s;
        for (int j = 0; j < 128; j++) row[j] *= inv;
    }
    __syncthreads();

#pragma unroll
    for (int h = 0; h < 2; h++) {
        float z[8][8];
#pragma unroll
        for (int i = 0; i < 8; i++)
#pragma unroll
            for (int j = 0; j < 8; j++) z[i][j] = 0.0f;

        for (int j0 = 0; j0 < 128; j0 += 16) {
            const int vr = tid >> 5;
            const int vc = (tid & 31) << 2;
            float4 v0 = *(const float4*)(vb + (size_t)(j0 + vr)     * N_V + h * 128 + vc);
            float4 v1 = *(const float4*)(vb + (size_t)(j0 + vr + 8) * N_V + h * 128 + vc);
            __syncthreads();
            *(float4*)&Bs[(vr)     * 132 + vc] = v0;
            *(float4*)&Bs[(vr + 8) * 132 + vc] = v1;
            __syncthreads();

#pragma unroll
            for (int jj = 0; jj < 16; jj++) {
                float a[8];
#pragma unroll
                for (int i = 0; i < 8; i++)
                    a[i] = S[(size_t)(tm * 8 + i) * 129 + j0 + jj];
                float4 b0 = *(const float4*)&Bs[jj * 132 + tn * 8];
                float4 b1 = *(const float4*)&Bs[jj * 132 + tn * 8 + 4];
                float bvv[8] = {b0.x, b0.y, b0.z, b0.w, b1.x, b1.y, b1.z, b1.w};
#pragma unroll
                for (int i = 0; i < 8; i++)
#pragma unroll
                    for (int j = 0; j < 8; j++)
                        z[i][j] = fmaf(a[i], bvv[j], z[i][j]);
            }
        }

#pragma unroll
        for (int i = 0; i < 8; i++) {
            float4 o0 = make_float4(z[i][0], z[i][1], z[i][2], z[i][3]);
            float4 o1 = make_float4(z[i][4], z[i][5], z[i][6], z[i][7]);
            *(float4*)(ob + (size_t)(tm * 8 + i) * N_V + h * 128 + tn * 8)     = o0;
            *(float4*)(ob + (size_t)(tm * 8 + i) * N_V + h * 128 + tn * 8 + 4) = o1;
        }
    }
}

// ---------------------------------------------------------------------------
extern "C" void kernel_launch(void* const* d_in, const int* in_sizes, int n_in,
                              void* d_out, int out_size)
{
    const float* x  = (const float*)d_in[0];
    const float* Wq = (const float*)d_in[1];
    const float* bq = (const float*)d_in[2];
    const float* Wk = (const float*)d_in[3];
    const float* bk = (const float*)d_in[4];
    const float* Wv = (const float*)d_in[5];
    const float* bv = (const float*)d_in[6];
    float* out = (float*)d_out;

    conv_x<<<4096, 256>>>(x);
    conv_w<<<dim3(64, 3), 256>>>(Wq, Wk, Wv);

    cudaFuncSetAttribute(gemm_mma, cudaFuncAttributeMaxDynamicSharedMemorySize,
                         GEMM_SMEM);
    gemm_mma<<<dim3(6, 1024), 256, GEMM_SMEM>>>(bq, bk, bv);

    const size_t smem2 = (size_t)(128 * 129 + 2 * 16 * 132) * sizeof(float);
    cudaFuncSetAttribute(attn_kernel, cudaFuncAttributeMaxDynamicSharedMemorySize,
                         (int)smem2);
    attn_kernel<<<BD, 256, smem2>>>(out);
}

// round 8
// speedup vs baseline: 2.4485x; 1.0624x over previous
#include <cuda_runtime.h>
#include <cuda_bf16.h>
#include <cstdint>

// Problem constants
#define T_DIM 1024
#define N_QK  256
#define N_V   256
#define C_DIM 128
#define BD    1024
#define M_TOT (BD * C_DIM)   // 131072

// ---------------------------------------------------------------------------
// Scratch (__device__ globals; alloc-free rule)
// q/k/v stored as bf16 hi/lo pairs (split done in GEMM epilogue)
// ---------------------------------------------------------------------------
__device__ __align__(16) __nv_bfloat16 g_qh[(size_t)M_TOT * N_QK];
__device__ __align__(16) __nv_bfloat16 g_ql[(size_t)M_TOT * N_QK];
__device__ __align__(16) __nv_bfloat16 g_kh[(size_t)M_TOT * N_QK];
__device__ __align__(16) __nv_bfloat16 g_kl[(size_t)M_TOT * N_QK];
__device__ __align__(16) __nv_bfloat16 g_vh[(size_t)M_TOT * N_V];
__device__ __align__(16) __nv_bfloat16 g_vl[(size_t)M_TOT * N_V];

__device__ __align__(16) __nv_bfloat16 g_xh[(size_t)M_TOT * T_DIM];
__device__ __align__(16) __nv_bfloat16 g_xl[(size_t)M_TOT * T_DIM];
__device__ __align__(16) __nv_bfloat16 g_wh[3 * 256 * T_DIM];
__device__ __align__(16) __nv_bfloat16 g_wl[3 * 256 * T_DIM];

// ---------------------------------------------------------------------------
// Helpers
// ---------------------------------------------------------------------------
__device__ __forceinline__ uint32_t smem_u32(const void* p) {
    uint32_t a;
    asm("{ .reg .u64 t; cvta.to.shared.u64 t, %1; cvt.u32.u64 %0, t; }"
        : "=r"(a) : "l"(p));
    return a;
}
__device__ __forceinline__ void cp16(uint32_t dst, const void* src) {
    asm volatile("cp.async.cg.shared.global [%0], [%1], 16;"
                 :: "r"(dst), "l"(src) : "memory");
}
#define CP_COMMIT() asm volatile("cp.async.commit_group;" ::: "memory")
#define CP_WAIT1()  asm volatile("cp.async.wait_group 1;" ::: "memory")

__device__ __forceinline__ void ldsm4(uint32_t* r, uint32_t addr) {
    asm volatile("ldmatrix.sync.aligned.m8n8.x4.shared.b16 {%0,%1,%2,%3}, [%4];"
                 : "=r"(r[0]), "=r"(r[1]), "=r"(r[2]), "=r"(r[3]) : "r"(addr));
}
__device__ __forceinline__ void ldsm4t(uint32_t* r, uint32_t addr) {
    asm volatile("ldmatrix.sync.aligned.m8n8.x4.trans.shared.b16 {%0,%1,%2,%3}, [%4];"
                 : "=r"(r[0]), "=r"(r[1]), "=r"(r[2]), "=r"(r[3]) : "r"(addr));
}
__device__ __forceinline__ void mma16816(float* d, const uint32_t* a,
                                         uint32_t b0, uint32_t b1) {
    asm volatile(
        "mma.sync.aligned.m16n8k16.row.col.f32.bf16.bf16.f32 "
        "{%0,%1,%2,%3}, {%4,%5,%6,%7}, {%8,%9}, {%0,%1,%2,%3};"
        : "+f"(d[0]), "+f"(d[1]), "+f"(d[2]), "+f"(d[3])
        : "r"(a[0]), "r"(a[1]), "r"(a[2]), "r"(a[3]), "r"(b0), "r"(b1));
}
__device__ __forceinline__ uint32_t pack_bf2(__nv_bfloat16 a, __nv_bfloat16 b) {
    return (uint32_t)__bfloat16_as_ushort(a) | ((uint32_t)__bfloat16_as_ushort(b) << 16);
}

// ---------------------------------------------------------------------------
// Convert kernels: fp32 -> bf16 hi/lo split
// ---------------------------------------------------------------------------
__global__ void __launch_bounds__(256) conv_x(const float* __restrict__ x)
{
    const size_t n4 = (size_t)M_TOT * T_DIM / 4;
    const size_t stride = (size_t)gridDim.x * blockDim.x;
    uint2* __restrict__ xh = (uint2*)g_xh;
    uint2* __restrict__ xl = (uint2*)g_xl;
    for (size_t i = (size_t)blockIdx.x * blockDim.x + threadIdx.x; i < n4; i += stride) {
        float4 f = ((const float4*)x)[i];
        __nv_bfloat16 h0 = __float2bfloat16(f.x);
        __nv_bfloat16 h1 = __float2bfloat16(f.y);
        __nv_bfloat16 h2 = __float2bfloat16(f.z);
        __nv_bfloat16 h3 = __float2bfloat16(f.w);
        __nv_bfloat16 l0 = __float2bfloat16(f.x - __bfloat162float(h0));
        __nv_bfloat16 l1 = __float2bfloat16(f.y - __bfloat162float(h1));
        __nv_bfloat16 l2 = __float2bfloat16(f.z - __bfloat162float(h2));
        __nv_bfloat16 l3 = __float2bfloat16(f.w - __bfloat162float(h3));
        xh[i] = make_uint2(pack_bf2(h0, h1), pack_bf2(h2, h3));
        xl[i] = make_uint2(pack_bf2(l0, l1), pack_bf2(l2, l3));
    }
}

__global__ void __launch_bounds__(256) conv_w(const float* __restrict__ Wq,
                                              const float* __restrict__ Wk,
                                              const float* __restrict__ Wv)
{
    const int mat = blockIdx.y;
    const float* W = (mat == 0) ? Wq : (mat == 1) ? Wk : Wv;
    const size_t n4 = 256 * T_DIM / 4;
    const size_t base = (size_t)mat * n4;
    uint2* __restrict__ wh = (uint2*)g_wh;
    uint2* __restrict__ wl = (uint2*)g_wl;
    for (size_t i = (size_t)blockIdx.x * blockDim.x + threadIdx.x; i < n4;
         i += (size_t)gridDim.x * blockDim.x) {
        float4 f = ((const float4*)W)[i];
        __nv_bfloat16 h0 = __float2bfloat16(f.x);
        __nv_bfloat16 h1 = __float2bfloat16(f.y);
        __nv_bfloat16 h2 = __float2bfloat16(f.z);
        __nv_bfloat16 h3 = __float2bfloat16(f.w);
        __nv_bfloat16 l0 = __float2bfloat16(f.x - __bfloat162float(h0));
        __nv_bfloat16 l1 = __float2bfloat16(f.y - __bfloat162float(h1));
        __nv_bfloat16 l2 = __float2bfloat16(f.z - __bfloat162float(h2));
        __nv_bfloat16 l3 = __float2bfloat16(f.w - __bfloat162float(h3));
        wh[base + i] = make_uint2(pack_bf2(h0, h1), pack_bf2(h2, h3));
        wl[base + i] = make_uint2(pack_bf2(l0, l1), pack_bf2(l2, l3));
    }
}

// ---------------------------------------------------------------------------
// HMMA GEMM (mainloop unchanged from R5): Y tile = X @ W^T + bias,
// epilogue splits the fp32 result into bf16 hi/lo and stores both.
// ---------------------------------------------------------------------------
#define ROW_B   80
#define TILE_B  (128 * ROW_B)
#define OFF_AH  0
#define OFF_AL  (1 * TILE_B)
#define OFF_BH  (2 * TILE_B)
#define OFF_BL  (3 * TILE_B)
#define STAGE_B (4 * TILE_B)
#define GEMM_SMEM (2 * STAGE_B)
#define NCHUNK  32

__device__ __forceinline__ void load_chunk(
    uint32_t st, const __nv_bfloat16* __restrict__ xh,
    const __nv_bfloat16* __restrict__ xl,
    const __nv_bfloat16* __restrict__ wh,
    const __nv_bfloat16* __restrict__ wl, int k0, int tid)
{
#pragma unroll
    for (int t = 0; t < 2; t++) {
        int op = tid + t * 256;
        int r  = op >> 2;
        int ch = op & 3;
        uint32_t doff = (uint32_t)(r * ROW_B + ch * 16);
        size_t soff = (size_t)r * T_DIM + k0 + ch * 8;
        cp16(st + OFF_AH + doff, xh + soff);
        cp16(st + OFF_AL + doff, xl + soff);
        cp16(st + OFF_BH + doff, wh + soff);
        cp16(st + OFF_BL + doff, wl + soff);
    }
}

__global__ void __launch_bounds__(256, 2) gemm_mma(
    const float* __restrict__ bq, const float* __restrict__ bk,
    const float* __restrict__ bv)
{
    extern __shared__ __align__(16) char dyn[];

    const int tid  = threadIdx.x;
    const int lane = tid & 31;
    const int wid  = tid >> 5;
    const int mat  = blockIdx.x >> 1;
    const int bn   = blockIdx.x & 1;
    const int bm   = blockIdx.y;

    const int wm = (wid >> 2) * 64;
    const int wn = (wid & 3) * 32;

    const __nv_bfloat16* xh = g_xh + (size_t)bm * 128 * T_DIM;
    const __nv_bfloat16* xl = g_xl + (size_t)bm * 128 * T_DIM;
    const __nv_bfloat16* wh = g_wh + ((size_t)mat * 256 + bn * 128) * T_DIM;
    const __nv_bfloat16* wl = g_wl + ((size_t)mat * 256 + bn * 128) * T_DIM;
    const float* bias = (mat == 0) ? bq : (mat == 1) ? bk : bv;
    __nv_bfloat16* outh = ((mat == 0) ? g_qh : (mat == 1) ? g_kh : g_vh)
                          + (size_t)bm * 128 * 256 + bn * 128;
    __nv_bfloat16* outl = ((mat == 0) ? g_ql : (mat == 1) ? g_kl : g_vl)
                          + (size_t)bm * 128 * 256 + bn * 128;

    const uint32_t sbase = smem_u32(dyn);

    float acc[4][4][4];
#pragma unroll
    for (int i = 0; i < 4; i++)
#pragma unroll
        for (int j = 0; j < 4; j++)
#pragma unroll
            for (int r = 0; r < 4; r++) acc[i][j][r] = 0.0f;

    const uint32_t aoff = (uint32_t)((wm + (lane & 15)) * ROW_B + (lane >> 4) * 16);
    const uint32_t boff = (uint32_t)((wn + ((lane >> 4) << 3) + (lane & 7)) * ROW_B
                                     + ((lane >> 3) & 1) * 16);

    load_chunk(sbase + 0 * STAGE_B, xh, xl, wh, wl, 0, tid);
    CP_COMMIT();
    load_chunk(sbase + 1 * STAGE_B, xh, xl, wh, wl, 32, tid);
    CP_COMMIT();

    for (int c = 0; c < NCHUNK; c++) {
        const uint32_t st = sbase + (c & 1) * STAGE_B;
        CP_WAIT1();
        __syncthreads();

#pragma unroll
        for (int ks = 0; ks < 2; ks++) {
            const uint32_t kadd = (uint32_t)(ks * 32);
            uint32_t ah[4][4], bh[2][4];
#pragma unroll
            for (int mi = 0; mi < 4; mi++)
                ldsm4(ah[mi], st + OFF_AH + aoff + mi * (16 * ROW_B) + kadd);
#pragma unroll
            for (int np = 0; np < 2; np++)
                ldsm4(bh[np], st + OFF_BH + boff + np * (16 * ROW_B) + kadd);
#pragma unroll
            for (int mi = 0; mi < 4; mi++)
#pragma unroll
                for (int nj = 0; nj < 4; nj++)
                    mma16816(acc[mi][nj], ah[mi], bh[nj >> 1][(nj & 1) * 2],
                             bh[nj >> 1][(nj & 1) * 2 + 1]);

            uint32_t bl[2][4];
#pragma unroll
            for (int np = 0; np < 2; np++)
                ldsm4(bl[np], st + OFF_BL + boff + np * (16 * ROW_B) + kadd);
#pragma unroll
            for (int mi = 0; mi < 4; mi++)
#pragma unroll
                for (int nj = 0; nj < 4; nj++)
                    mma16816(acc[mi][nj], ah[mi], bl[nj >> 1][(nj & 1) * 2],
                             bl[nj >> 1][(nj & 1) * 2 + 1]);

            uint32_t al[4][4];
#pragma unroll
            for (int mi = 0; mi < 4; mi++)
                ldsm4(al[mi], st + OFF_AL + aoff + mi * (16 * ROW_B) + kadd);
#pragma unroll
            for (int mi = 0; mi < 4; mi++)
#pragma unroll
                for (int nj = 0; nj < 4; nj++)
                    mma16816(acc[mi][nj], al[mi], bh[nj >> 1][(nj & 1) * 2],
                             bh[nj >> 1][(nj & 1) * 2 + 1]);
        }

        __syncthreads();
        if (c + 2 < NCHUNK)
            load_chunk(st, xh, xl, wh, wl, (c + 2) * 32, tid);
        CP_COMMIT();
    }

    // Epilogue: bias add, split to bf16 hi/lo, store both
    const int rq = lane >> 2;
    const int cq = (lane & 3) * 2;
#pragma unroll
    for (int nj = 0; nj < 4; nj++) {
        const int col = wn + nj * 8 + cq;
        const float b0 = bias[bn * 128 + col];
        const float b1 = bias[bn * 128 + col + 1];
#pragma unroll
        for (int mi = 0; mi < 4; mi++) {
            const int row = wm + mi * 16 + rq;
#pragma unroll
            for (int half = 0; half < 2; half++) {
                const float v0 = acc[mi][nj][half * 2 + 0] + b0;
                const float v1 = acc[mi][nj][half * 2 + 1] + b1;
                __nv_bfloat16 h0 = __float2bfloat16(v0);
                __nv_bfloat16 h1 = __float2bfloat16(v1);
                __nv_bfloat16 l0 = __float2bfloat16(v0 - __bfloat162float(h0));
                __nv_bfloat16 l1 = __float2bfloat16(v1 - __bfloat162float(h1));
                const size_t off = (size_t)(row + half * 8) * 256 + col;
                *(uint32_t*)(outh + off) = pack_bf2(h0, h1);
                *(uint32_t*)(outl + off) = pack_bf2(l0, l1);
            }
        }
    }
}

// ---------------------------------------------------------------------------
// Tensor-core attention: one CTA per (b,d), 256 threads (8 warps, 2x4)
// Phase 1: S = q@k^T (bf16 3-pass split, fp32 acc), K=256 in 8 chunks
// softmax (fp32 smem), split S -> bf16 hi/lo
// Phase 2: Z = S@V (bf16 3-pass split), V B-fragments via ldmatrix.trans
// ---------------------------------------------------------------------------
#define P1_ROWB  80
#define P1_TILE  (128 * P1_ROWB)        // 10240
#define P1_QH    0
#define P1_QL    (1 * P1_TILE)
#define P1_KH    (2 * P1_TILE)
#define P1_KL    (3 * P1_TILE)
#define P1_STAGE (4 * P1_TILE)          // 40960
#define R1_SIZE  (2 * P1_STAGE)         // 81920

#define S_PITCH  136                    // bf16 elems (272B rows)
#define SH_OFF   0
#define SL_OFF   (128 * S_PITCH * 2)    // 34816 (within R1, after phase 1)

#define R2_OFF   R1_SIZE
#define SF_PITCH 130                    // fp32 elems
#define V_PITCHB 528                    // bytes per V smem row (256 bf16 + pad)
#define V_TILE   (32 * V_PITCHB)        // 16896
#define V_STAGE  (2 * V_TILE)           // 33792 (hi tile + lo tile)
#define ATTN_SMEM (R1_SIZE + 2 * V_STAGE)   // 149504

__device__ __forceinline__ void p1_load(
    uint32_t st, const __nv_bfloat16* __restrict__ qh,
    const __nv_bfloat16* __restrict__ ql,
    const __nv_bfloat16* __restrict__ kh,
    const __nv_bfloat16* __restrict__ kl, int k0, int tid)
{
#pragma unroll
    for (int t = 0; t < 2; t++) {
        int op = tid + t * 256;
        int r  = op >> 2;
        int ch = op & 3;
        uint32_t doff = (uint32_t)(r * P1_ROWB + ch * 16);
        size_t soff = (size_t)r * N_QK + k0 + ch * 8;
        cp16(st + P1_QH + doff, qh + soff);
        cp16(st + P1_QL + doff, ql + soff);
        cp16(st + P1_KH + doff, kh + soff);
        cp16(st + P1_KL + doff, kl + soff);
    }
}

__device__ __forceinline__ void v_load(
    uint32_t st, const __nv_bfloat16* __restrict__ vh,
    const __nv_bfloat16* __restrict__ vl, int k0, int tid)
{
#pragma unroll
    for (int t = 0; t < 4; t++) {
        int op = tid + t * 256;          // 0..1023
        int r  = op >> 5;                // 0..31
        int ch = op & 31;                // 0..31 (16B chunks of 512B row)
        uint32_t doff = (uint32_t)(r * V_PITCHB + ch * 16);
        size_t soff = (size_t)(k0 + r) * N_V + ch * 8;
        cp16(st + doff, vh + soff);
        cp16(st + V_TILE + doff, vl + soff);
    }
}

__global__ void __launch_bounds__(256) attn_tc(float* __restrict__ out)
{
    extern __shared__ __align__(16) char dyn[];
    const uint32_t sb = smem_u32(dyn);

    const int tid  = threadIdx.x;
    const int lane = tid & 31;
    const int wid  = tid >> 5;
    const int bd   = blockIdx.x;

    const __nv_bfloat16* qh = g_qh + (size_t)bd * C_DIM * N_QK;
    const __nv_bfloat16* ql = g_ql + (size_t)bd * C_DIM * N_QK;
    const __nv_bfloat16* kh = g_kh + (size_t)bd * C_DIM * N_QK;
    const __nv_bfloat16* kl = g_kl + (size_t)bd * C_DIM * N_QK;
    const __nv_bfloat16* vh = g_vh + (size_t)bd * C_DIM * N_V;
    const __nv_bfloat16* vl = g_vl + (size_t)bd * C_DIM * N_V;
    float* ob = out + (size_t)bd * C_DIM * N_V;

    const int wm = (wid >> 2) * 64;      // 0 or 64
    const int wn = (wid & 3) * 32;       // phase-1 n tile
    const int rq = lane >> 2;
    const int cq = (lane & 3) * 2;

    // ================= Phase 1: S = q @ k^T =================
    {
        float acc[4][4][4];
#pragma unroll
        for (int i = 0; i < 4; i++)
#pragma unroll
            for (int j = 0; j < 4; j++)
#pragma unroll
                for (int r = 0; r < 4; r++) acc[i][j][r] = 0.0f;

        const uint32_t aoff = (uint32_t)((wm + (lane & 15)) * P1_ROWB + (lane >> 4) * 16);
        const uint32_t boff = (uint32_t)((wn + ((lane >> 4) << 3) + (lane & 7)) * P1_ROWB
                                         + ((lane >> 3) & 1) * 16);

        p1_load(sb + 0 * P1_STAGE, qh, ql, kh, kl, 0, tid);
        CP_COMMIT();
        p1_load(sb + 1 * P1_STAGE, qh, ql, kh, kl, 32, tid);
        CP_COMMIT();

        for (int c = 0; c < 8; c++) {
            const uint32_t st = sb + (c & 1) * P1_STAGE;
            CP_WAIT1();
            __syncthreads();

#pragma unroll
            for (int ks = 0; ks < 2; ks++) {
                const uint32_t kadd = (uint32_t)(ks * 32);
                uint32_t ah[4][4], bh[2][4];
#pragma unroll
                for (int mi = 0; mi < 4; mi++)
                    ldsm4(ah[mi], st + P1_QH + aoff + mi * (16 * P1_ROWB) + kadd);
#pragma unroll
                for (int np = 0; np < 2; np++)
                    ldsm4(bh[np], st + P1_KH + boff + np * (16 * P1_ROWB) + kadd);
#pragma unroll
                for (int mi = 0; mi < 4; mi++)
#pragma unroll
                    for (int nj = 0; nj < 4; nj++)
                        mma16816(acc[mi][nj], ah[mi], bh[nj >> 1][(nj & 1) * 2],
                                 bh[nj >> 1][(nj & 1) * 2 + 1]);

                uint32_t bl[2][4];
#pragma unroll
                for (int np = 0; np < 2; np++)
                    ldsm4(bl[np], st + P1_KL + boff + np * (16 * P1_ROWB) + kadd);
#pragma unroll
                for (int mi = 0; mi < 4; mi++)
#pragma unroll
                    for (int nj = 0; nj < 4; nj++)
                        mma16816(acc[mi][nj], ah[mi], bl[nj >> 1][(nj & 1) * 2],
                                 bl[nj >> 1][(nj & 1) * 2 + 1]);

                uint32_t al[4][4];
#pragma unroll
                for (int mi = 0; mi < 4; mi++)
                    ldsm4(al[mi], st + P1_QL + aoff + mi * (16 * P1_ROWB) + kadd);
#pragma unroll
                for (int mi = 0; mi < 4; mi++)
#pragma unroll
                    for (int nj = 0; nj < 4; nj++)
                        mma16816(acc[mi][nj], al[mi], bh[nj >> 1][(nj & 1) * 2],
                                 bh[nj >> 1][(nj & 1) * 2 + 1]);
            }

            __syncthreads();
            if (c + 2 < 8)
                p1_load(st, qh, ql, kh, kl, (c + 2) * 32, tid);
            CP_COMMIT();
        }

        // Write scaled S (fp32) to smem region 2
        float* Sf = (float*)(dyn + R2_OFF);
        const float scale = 0.0625f;     // 1/sqrt(256)
#pragma unroll
        for (int nj = 0; nj < 4; nj++) {
            const int col = wn + nj * 8 + cq;
#pragma unroll
            for (int mi = 0; mi < 4; mi++) {
                const int row = wm + mi * 16 + rq;
                Sf[row * SF_PITCH + col]           = acc[mi][nj][0] * scale;
                Sf[row * SF_PITCH + col + 1]       = acc[mi][nj][1] * scale;
                Sf[(row + 8) * SF_PITCH + col]     = acc[mi][nj][2] * scale;
                Sf[(row + 8) * SF_PITCH + col + 1] = acc[mi][nj][3] * scale;
            }
        }
    }
    __syncthreads();

    // ================= Softmax (rows, fp32) =================
    {
        float* Sf = (float*)(dyn + R2_OFF);
        if (tid < 128) {
            float* row = Sf + tid * SF_PITCH;
            float m = -1e30f;
#pragma unroll 4
            for (int j = 0; j < 128; j++) m = fmaxf(m, row[j]);
            float s = 0.0f;
#pragma unroll 4
            for (int j = 0; j < 128; j++) { float e = __expf(row[j] - m); row[j] = e; s += e; }
            float inv = 1.0f / s;
#pragma unroll 4
            for (int j = 0; j < 128; j++) row[j] *= inv;
        }
    }
    __syncthreads();

    // ================= Split S -> bf16 hi/lo (region 1) =================
    {
        const float* Sf = (const float*)(dyn + R2_OFF);
        const int row = tid >> 1;
        const int c0  = (tid & 1) * 64;
#pragma unroll
        for (int j = 0; j < 64; j += 2) {
            float f0 = Sf[row * SF_PITCH + c0 + j];
            float f1 = Sf[row * SF_PITCH + c0 + j + 1];
            __nv_bfloat16 h0 = __float2bfloat16(f0);
            __nv_bfloat16 h1 = __float2bfloat16(f1);
            __nv_bfloat16 l0 = __float2bfloat16(f0 - __bfloat162float(h0));
            __nv_bfloat16 l1 = __float2bfloat16(f1 - __bfloat162float(h1));
            *(uint32_t*)(dyn + SH_OFF + (size_t)(row * S_PITCH + c0 + j) * 2) = pack_bf2(h0, h1);
            *(uint32_t*)(dyn + SL_OFF + (size_t)(row * S_PITCH + c0 + j) * 2) = pack_bf2(l0, l1);
        }
    }
    __syncthreads();   // conversion done before V stages overwrite region 2

    // ================= Phase 2: Z = S @ V =================
    {
        const int wn2 = (wid & 3) * 64;     // 64 output cols per warp
        float acc2[4][8][4];
#pragma unroll
        for (int i = 0; i < 4; i++)
#pragma unroll
            for (int j = 0; j < 8; j++)
#pragma unroll
                for (int r = 0; r < 4; r++) acc2[i][j][r] = 0.0f;

        const uint32_t aoff2 = (uint32_t)((wm + (lane & 15)) * (S_PITCH * 2)
                                          + (lane >> 4) * 16);
        // trans B: lanes 0-15 -> k rows, lane>>4 -> n +8
        const uint32_t bro = (uint32_t)((lane & 15) * V_PITCHB + (lane >> 4) * 16);

        v_load(sb + R2_OFF + 0 * V_STAGE, vh, vl, 0, tid);
        CP_COMMIT();
        v_load(sb + R2_OFF + 1 * V_STAGE, vh, vl, 32, tid);
        CP_COMMIT();

        for (int c = 0; c < 4; c++) {
            const uint32_t st = sb + R2_OFF + (c & 1) * V_STAGE;
            CP_WAIT1();
            __syncthreads();

#pragma unroll
            for (int ks = 0; ks < 2; ks++) {
                const uint32_t acol = (uint32_t)((c * 32 + ks * 16) * 2);
                const uint32_t brow = (uint32_t)(ks * 16 * V_PITCHB);

                uint32_t ah[4][4], bh[4][4];
#pragma unroll
                for (int mi = 0; mi < 4; mi++)
                    ldsm4(ah[mi], sb + SH_OFF + aoff2 + mi * (16 * S_PITCH * 2) + acol);
#pragma unroll
                for (int nb = 0; nb < 4; nb++)
                    ldsm4t(bh[nb], st + brow + bro + (uint32_t)((wn2 + nb * 16) * 2));
#pragma unroll
                for (int mi = 0; mi < 4; mi++)
#pragma unroll
                    for (int nj = 0; nj < 8; nj++)
                        mma16816(acc2[mi][nj], ah[mi], bh[nj >> 1][(nj & 1) * 2],
                                 bh[nj >> 1][(nj & 1) * 2 + 1]);

                uint32_t bl[4][4];
#pragma unroll
                for (int nb = 0; nb < 4; nb++)
                    ldsm4t(bl[nb], st + V_TILE + brow + bro + (uint32_t)((wn2 + nb * 16) * 2));
#pragma unroll
                for (int mi = 0; mi < 4; mi++)
#pragma unroll
                    for (int nj = 0; nj < 8; nj++)
                        mma16816(acc2[mi][nj], ah[mi], bl[nj >> 1][(nj & 1) * 2],
                                 bl[nj >> 1][(nj & 1) * 2 + 1]);

                uint32_t al[4][4];
#pragma unroll
                for (int mi = 0; mi < 4; mi++)
                    ldsm4(al[mi], sb + SL_OFF + aoff2 + mi * (16 * S_PITCH * 2) + acol);
#pragma unroll
                for (int mi = 0; mi < 4; mi++)
#pragma unroll
                    for (int nj = 0; nj < 8; nj++)
                        mma16816(acc2[mi][nj], al[mi], bh[nj >> 1][(nj & 1) * 2],
                                 bh[nj >> 1][(nj & 1) * 2 + 1]);
            }

            __syncthreads();
            if (c + 2 < 4)
                v_load(st, vh, vl, (c + 2) * 32, tid);
            CP_COMMIT();
        }

        // Epilogue: fp32 out
#pragma unroll
        for (int nj = 0; nj < 8; nj++) {
            const int col = wn2 + nj * 8 + cq;
#pragma unroll
            for (int mi = 0; mi < 4; mi++) {
                const int row = wm + mi * 16 + rq;
                *(float2*)(ob + (size_t)row * N_V + col) =
                    make_float2(acc2[mi][nj][0], acc2[mi][nj][1]);
                *(float2*)(ob + (size_t)(row + 8) * N_V + col) =
                    make_float2(acc2[mi][nj][2], acc2[mi][nj][3]);
            }
        }
    }
}

// ---------------------------------------------------------------------------
extern "C" void kernel_launch(void* const* d_in, const int* in_sizes, int n_in,
                              void* d_out, int out_size)
{
    const float* x  = (const float*)d_in[0];
    const float* Wq = (const float*)d_in[1];
    const float* bq = (const float*)d_in[2];
    const float* Wk = (const float*)d_in[3];
    const float* bk = (const float*)d_in[4];
    const float* Wv = (const float*)d_in[5];
    const float* bv = (const float*)d_in[6];
    float* out = (float*)d_out;

    conv_x<<<4096, 256>>>(x);
    conv_w<<<dim3(64, 3), 256>>>(Wq, Wk, Wv);

    cudaFuncSetAttribute(gemm_mma, cudaFuncAttributeMaxDynamicSharedMemorySize,
                         GEMM_SMEM);
    gemm_mma<<<dim3(6, 1024), 256, GEMM_SMEM>>>(bq, bk, bv);

    cudaFuncSetAttribute(attn_tc, cudaFuncAttributeMaxDynamicSharedMemorySize,
                         ATTN_SMEM);
    attn_tc<<<BD, 256, ATTN_SMEM>>>(out);
}